// round 6
// baseline (speedup 1.0000x reference)
#include <cuda_runtime.h>
#include <math.h>

#define NN 10000
#define NE 160000
#define CC 128
#define DD 64
#define KAUG 136
#define HID 256
#define TPWN 512
#define MROW 1024          // m0 (256) + m1 (256*3)
#define SC_OFF (NN * 512)  // message is N*128*4 = N*512 floats, sc follows

// -------- device scratch (allocation-free rule: static __device__ globals) ----
// NOTE: these symbols are ONLY referenced from device code. Passing them as
// host-side kernel arguments binds the host shadow variable (ATS-reachable on
// GB300, so it silently "works" against host memory) — that was the round-5 bug.
__device__ float g_u0[NN * CC];
__device__ float g_u1[NN * CC * 3];
__device__ float g_down[NN * DD];
__device__ float g_hA[NE * HID];
__device__ float g_hB[NE * HID];
__device__ float g_tpw[NE * TPWN];
__device__ float g_m[NN * MROW];

// ---------------------------------------------------------------------------
// zero the segment-sum accumulator (must run every launch: deterministic)
// ---------------------------------------------------------------------------
__global__ void zero_m_kernel() {
    int idx = blockIdx.x * blockDim.x + threadIdx.x;
    int stride = gridDim.x * blockDim.x;
    for (int i = idx; i < NN * MROW; i += stride) g_m[i] = 0.0f;
}

// ---------------------------------------------------------------------------
// Node transforms: u0, u1, down (to scratch) + sc (directly to output)
// One block = 8 nodes, 128 threads (thread = output channel v)
// ---------------------------------------------------------------------------
__global__ void node_kernel(const float* __restrict__ nf,
                            const float* __restrict__ Wu0,
                            const float* __restrict__ Wu1,
                            const float* __restrict__ Wd,
                            const float* __restrict__ Ws0,
                            const float* __restrict__ Ws1,
                            float* __restrict__ out) {
    const int NB = 8;
    __shared__ float sx0[NB][CC];
    __shared__ float sx1[NB][CC * 3];
    int n0 = blockIdx.x * NB;
    int v = threadIdx.x;  // 0..127

    // stage node features: x0 = nf[:, :128], x1 = nf[:, 128:] (u-major, i fastest)
    for (int j = v; j < NB * 512; j += 128) {
        int nb = j >> 9;
        int k = j & 511;
        float val = nf[(size_t)(n0 + nb) * 512 + k];
        if (k < 128) sx0[nb][k] = val;
        else sx1[nb][k - 128] = val;
    }
    __syncthreads();

    const float inv_c = 0.08838834764831845f;  // 1/sqrt(128)

    // ---- pass 1: scalar channels (u0, sc0, down) ----
    float au0[NB], as0[NB], ad[NB];
#pragma unroll
    for (int nb = 0; nb < NB; nb++) { au0[nb] = 0.f; as0[nb] = 0.f; ad[nb] = 0.f; }
    for (int u = 0; u < CC; u++) {
        float w0 = Wu0[u * CC + v];
        float ws = Ws0[u * CC + v];
        float wd = (v < DD) ? Wd[u * DD + v] : 0.f;
#pragma unroll
        for (int nb = 0; nb < NB; nb++) {
            float x = sx0[nb][u];
            au0[nb] += x * w0;
            as0[nb] += x * ws;
            ad[nb] += x * wd;
        }
    }
#pragma unroll
    for (int nb = 0; nb < NB; nb++) {
        int n = n0 + nb;
        g_u0[n * CC + v] = au0[nb] * inv_c;
        out[SC_OFF + (size_t)n * 512 + v] = as0[nb] * inv_c;
        if (v < DD) g_down[n * DD + v] = ad[nb] * inv_c;
    }

    // ---- pass 2: vector channels (u1, sc1), 3 components ----
    float au1[NB][3], as1[NB][3];
#pragma unroll
    for (int nb = 0; nb < NB; nb++)
#pragma unroll
        for (int i = 0; i < 3; i++) { au1[nb][i] = 0.f; as1[nb][i] = 0.f; }
    for (int u = 0; u < CC; u++) {
        float wu = Wu1[u * CC + v];
        float ws = Ws1[u * CC + v];
#pragma unroll
        for (int nb = 0; nb < NB; nb++) {
#pragma unroll
            for (int i = 0; i < 3; i++) {
                float x = sx1[nb][u * 3 + i];
                au1[nb][i] += x * wu;
                as1[nb][i] += x * ws;
            }
        }
    }
#pragma unroll
    for (int nb = 0; nb < NB; nb++) {
        int n = n0 + nb;
#pragma unroll
        for (int i = 0; i < 3; i++) {
            g_u1[n * (CC * 3) + v * 3 + i] = au1[nb][i] * inv_c;
            out[SC_OFF + (size_t)n * 512 + 128 + v * 3 + i] = as1[nb][i] * inv_c;
        }
    }
}

// ---------------------------------------------------------------------------
// Tiled SGEMM: C[M,Nc] = act( A[M,K] @ B[K,Nc] * scale )
// BM=BN=64, BK=16, 256 threads, 4x4 per-thread tile.
// SRC: 0 = gather rows on the fly ([edge_feats(8) | down[s](64) | down[r](64)]),
//      1 = g_hA, 2 = g_hB.   DST: 1 = g_hA, 2 = g_hB, 3 = g_tpw.
// Scratch pointers resolved IN DEVICE CODE (true device symbols).
// ---------------------------------------------------------------------------
template <int SRC, int DST, bool SILU>
__global__ void mlp_gemm(const float* __restrict__ B,
                         int Nc, int K, float scale,
                         const float* __restrict__ edge_feats,
                         const int* __restrict__ edge_index) {
    const float* A = (SRC == 1) ? g_hA : (SRC == 2) ? g_hB : nullptr;
    float* Cout = (DST == 1) ? g_hA : (DST == 2) ? g_hB : g_tpw;

    __shared__ float As[16][64];
    __shared__ float Bs[16][64];

    int tid = threadIdx.x;           // 0..255
    int tx = tid & 15;               // col group
    int ty = tid >> 4;               // row group
    int rowBase = blockIdx.y * 64;
    int colBase = blockIdx.x * 64;

    // A-load mapping: each thread one float4: row = tid/4, k0 = (tid%4)*4
    int aRow = tid >> 2;
    int aK0 = (tid & 3) * 4;
    // B-load mapping: k = tid/16, n0 = (tid%16)*4
    int bK = tid >> 4;
    int bN0 = (tid & 15) * 4;

    float acc[4][4];
#pragma unroll
    for (int m = 0; m < 4; m++)
#pragma unroll
        for (int n = 0; n < 4; n++) acc[m][n] = 0.f;

    int kTiles = (K + 15) / 16;
    for (int kt = 0; kt < kTiles; kt++) {
        int kb = kt * 16;
        // ---- load A tile ----
        {
            float4 v = make_float4(0.f, 0.f, 0.f, 0.f);
            int k0 = kb + aK0;
            int row = rowBase + aRow;
            if (k0 < K) {  // K % 4 == 0, so k0 < K implies a full float4 is valid
                if (SRC == 0) {
                    if (k0 < 8) {
                        v = *(const float4*)(edge_feats + (size_t)row * 8 + k0);
                    } else if (k0 < 72) {
                        int s = edge_index[row];
                        v = *(const float4*)(g_down + (size_t)s * DD + (k0 - 8));
                    } else {
                        int r = edge_index[NE + row];
                        v = *(const float4*)(g_down + (size_t)r * DD + (k0 - 72));
                    }
                } else {
                    v = *(const float4*)(A + (size_t)row * K + k0);
                }
            }
            As[aK0 + 0][aRow] = v.x;
            As[aK0 + 1][aRow] = v.y;
            As[aK0 + 2][aRow] = v.z;
            As[aK0 + 3][aRow] = v.w;
        }
        // ---- load B tile ----
        {
            float4 v = make_float4(0.f, 0.f, 0.f, 0.f);
            int kk = kb + bK;
            if (kk < K) v = *(const float4*)(B + (size_t)kk * Nc + colBase + bN0);
            *(float4*)&Bs[bK][bN0] = v;
        }
        __syncthreads();

#pragma unroll
        for (int k = 0; k < 16; k++) {
            float a[4], b[4];
#pragma unroll
            for (int m = 0; m < 4; m++) a[m] = As[k][ty * 4 + m];
#pragma unroll
            for (int n = 0; n < 4; n++) b[n] = Bs[k][tx * 4 + n];
#pragma unroll
            for (int m = 0; m < 4; m++)
#pragma unroll
                for (int n = 0; n < 4; n++) acc[m][n] += a[m] * b[n];
        }
        __syncthreads();
    }

    // ---- epilogue ----
#pragma unroll
    for (int m = 0; m < 4; m++) {
        int row = rowBase + ty * 4 + m;
        float4 v;
        float r[4];
#pragma unroll
        for (int n = 0; n < 4; n++) {
            float x = acc[m][n] * scale;
            if (SILU) x = x / (1.0f + expf(-x));
            r[n] = x;
        }
        v.x = r[0]; v.y = r[1]; v.z = r[2]; v.w = r[3];
        *(float4*)(Cout + (size_t)row * Nc + colBase + tx * 4) = v;
    }
}

// ---------------------------------------------------------------------------
// Edge tensor product + scatter-add (segment_sum) into g_m
// One block per edge, 128 threads (thread = channel c)
// ---------------------------------------------------------------------------
__global__ void edge_tp_kernel(const float* __restrict__ edge_attrs,
                               const int* __restrict__ edge_index) {
    int e = blockIdx.x;
    int c = threadIdx.x;

    int s = edge_index[e];
    int r = edge_index[NE + e];
    float y0 = edge_attrs[(size_t)e * 4 + 0];
    float y1x = edge_attrs[(size_t)e * 4 + 1];
    float y1y = edge_attrs[(size_t)e * 4 + 2];
    float y1z = edge_attrs[(size_t)e * 4 + 3];

    const float* tw = g_tpw + (size_t)e * TPWN;
    float w0 = tw[c];
    float w1 = tw[128 + c];
    float w2 = tw[256 + c];
    float w3 = tw[384 + c];

    float xs0 = g_u0[(size_t)s * CC + c];
    const float* u1p = g_u1 + (size_t)s * (CC * 3) + c * 3;
    float x1a = u1p[0], x1b = u1p[1], x1c = u1p[2];

    float* mrow = g_m + (size_t)r * MROW;
    const float rsqrt3 = 0.5773502691896258f;

    // o0a -> m0[c]
    atomicAdd(mrow + c, w0 * xs0 * y0);
    // o0b -> m0[128+c]
    float dot = x1a * y1x + x1b * y1y + x1c * y1z;
    atomicAdd(mrow + 128 + c, w3 * dot * rsqrt3);
    // o1a -> m1[c][i]
    float a = w1 * xs0;
    atomicAdd(mrow + 256 + c * 3 + 0, a * y1x);
    atomicAdd(mrow + 256 + c * 3 + 1, a * y1y);
    atomicAdd(mrow + 256 + c * 3 + 2, a * y1z);
    // o1b -> m1[128+c][i]
    float b = w2 * y0;
    atomicAdd(mrow + 256 + (128 + c) * 3 + 0, b * x1a);
    atomicAdd(mrow + 256 + (128 + c) * 3 + 1, b * x1b);
    atomicAdd(mrow + 256 + (128 + c) * 3 + 2, b * x1c);
}

// ---------------------------------------------------------------------------
// Final linear: message[n,v,0] = (m0 @ Wl0)/256 ; message[n,v,1..3] = (m1 @ Wl1)/256
// One block = 8 nodes, 128 threads (thread = output channel v)
// ---------------------------------------------------------------------------
__global__ void msg_kernel(const float* __restrict__ Wl0,
                           const float* __restrict__ Wl1,
                           float* __restrict__ out) {
    const int NB = 8;
    __shared__ float sm[NB][MROW];
    int n0 = blockIdx.x * NB;
    int v = threadIdx.x;

    for (int j = v; j < NB * MROW; j += 128) {
        sm[j >> 10][j & 1023] = g_m[(size_t)n0 * MROW + j];
    }
    __syncthreads();

    float m0acc[NB];
    float m1acc[NB][3];
#pragma unroll
    for (int nb = 0; nb < NB; nb++) {
        m0acc[nb] = 0.f;
#pragma unroll
        for (int i = 0; i < 3; i++) m1acc[nb][i] = 0.f;
    }

    for (int cc = 0; cc < 256; cc++) {
        float w0 = Wl0[cc * 128 + v];
        float w1 = Wl1[cc * 128 + v];
#pragma unroll
        for (int nb = 0; nb < NB; nb++) {
            m0acc[nb] += sm[nb][cc] * w0;
#pragma unroll
            for (int i = 0; i < 3; i++)
                m1acc[nb][i] += sm[nb][256 + cc * 3 + i] * w1;
        }
    }

    const float sc = 1.0f / 256.0f;  // (1/sqrt(256)) / AVG_NEIGH
#pragma unroll
    for (int nb = 0; nb < NB; nb++) {
        int n = n0 + nb;
        float4 v4;
        v4.x = m0acc[nb] * sc;
        v4.y = m1acc[nb][0] * sc;
        v4.z = m1acc[nb][1] * sc;
        v4.w = m1acc[nb][2] * sc;
        *(float4*)(out + (size_t)n * 512 + v * 4) = v4;
    }
}

// ---------------------------------------------------------------------------
extern "C" void kernel_launch(void* const* d_in, const int* in_sizes, int n_in,
                              void* d_out, int out_size) {
    const float* node_attrs = (const float*)d_in[0];  (void)node_attrs;
    const float* node_feats = (const float*)d_in[1];
    const float* edge_attrs = (const float*)d_in[2];
    const float* edge_feats = (const float*)d_in[3];
    const int*   edge_index = (const int*)d_in[4];
    const float* W_up0  = (const float*)d_in[5];
    const float* W_up1  = (const float*)d_in[6];
    const float* W_down = (const float*)d_in[7];
    const float* mlp_w1 = (const float*)d_in[8];
    const float* mlp_w2 = (const float*)d_in[9];
    const float* mlp_w3 = (const float*)d_in[10];
    const float* mlp_w4 = (const float*)d_in[11];
    const float* W_lin0 = (const float*)d_in[12];
    const float* W_lin1 = (const float*)d_in[13];
    const float* W_skip0 = (const float*)d_in[14];
    const float* W_skip1 = (const float*)d_in[15];
    float* out = (float*)d_out;

    // 1) zero the segment-sum accumulator
    zero_m_kernel<<<512, 256>>>();

    // 2) node transforms (+ writes sc part of output)
    node_kernel<<<NN / 8, 128>>>(node_feats, W_up0, W_up1, W_down, W_skip0, W_skip1, out);

    // 3) edge MLP: 4 GEMMs over E=160000 rows (scratch resolved device-side)
    float scale1 = 1.0f / sqrtf(136.0f);
    float scale2 = 1.0f / 16.0f;

    {
        dim3 grid(HID / 64, NE / 64);
        mlp_gemm<0, 1, true><<<grid, 256>>>(mlp_w1, HID, KAUG, scale1,
                                            edge_feats, edge_index);
        mlp_gemm<1, 2, true><<<grid, 256>>>(mlp_w2, HID, HID, scale2,
                                            nullptr, nullptr);
        mlp_gemm<2, 1, true><<<grid, 256>>>(mlp_w3, HID, HID, scale2,
                                            nullptr, nullptr);
    }
    {
        dim3 grid(TPWN / 64, NE / 64);
        mlp_gemm<1, 3, false><<<grid, 256>>>(mlp_w4, TPWN, HID, scale2,
                                             nullptr, nullptr);
    }

    // 4) edge tensor product + scatter
    edge_tp_kernel<<<NE, 128>>>(edge_attrs, edge_index);

    // 5) final linear -> message part of output
    msg_kernel<<<NN / 8, 128>>>(W_lin0, W_lin1, out);

    (void)in_sizes; (void)n_in; (void)out_size;
}

// round 7
// speedup vs baseline: 1.9036x; 1.9036x over previous
#include <cuda_runtime.h>
#include <math.h>

#define NN 10000
#define NE 160000
#define CC 128
#define DD 64
#define KAUG 136
#define HID 256
#define TPWN 512
#define MROW 1024          // m0 (256) + m1 (256*3)
#define SC_OFF (NN * 512)  // message is N*128*4 = N*512 floats, sc follows

// -------- device scratch (allocation-free rule: static __device__ globals) ----
// Only referenced from device code (host-side use binds the host shadow -> ATS
// silently reads host memory on GB300; that was the round-5 bug).
__device__ float g_u0[NN * CC];
__device__ float g_u1[NN * CC * 3];
__device__ float g_down[NN * DD];
__device__ float g_hA[NE * HID];
__device__ float g_hB[NE * HID];
__device__ float g_tpw[NE * TPWN];
__device__ float g_m[NN * MROW];

// ---------------------------------------------------------------------------
// zero the segment-sum accumulator (must run every launch: deterministic)
// ---------------------------------------------------------------------------
__global__ void zero_m_kernel() {
    int idx = blockIdx.x * blockDim.x + threadIdx.x;
    int stride = gridDim.x * blockDim.x;
    for (int i = idx; i < NN * MROW; i += stride) g_m[i] = 0.0f;
}

// ---------------------------------------------------------------------------
// Node transforms: u0, u1, down (to scratch) + sc (directly to output)
// ---------------------------------------------------------------------------
__global__ void node_kernel(const float* __restrict__ nf,
                            const float* __restrict__ Wu0,
                            const float* __restrict__ Wu1,
                            const float* __restrict__ Wd,
                            const float* __restrict__ Ws0,
                            const float* __restrict__ Ws1,
                            float* __restrict__ out) {
    const int NB = 8;
    __shared__ float sx0[NB][CC];
    __shared__ float sx1[NB][CC * 3];
    int n0 = blockIdx.x * NB;
    int v = threadIdx.x;  // 0..127

    for (int j = v; j < NB * 512; j += 128) {
        int nb = j >> 9;
        int k = j & 511;
        float val = nf[(size_t)(n0 + nb) * 512 + k];
        if (k < 128) sx0[nb][k] = val;
        else sx1[nb][k - 128] = val;
    }
    __syncthreads();

    const float inv_c = 0.08838834764831845f;  // 1/sqrt(128)

    float au0[NB], as0[NB], ad[NB];
#pragma unroll
    for (int nb = 0; nb < NB; nb++) { au0[nb] = 0.f; as0[nb] = 0.f; ad[nb] = 0.f; }
    for (int u = 0; u < CC; u++) {
        float w0 = Wu0[u * CC + v];
        float ws = Ws0[u * CC + v];
        float wd = (v < DD) ? Wd[u * DD + v] : 0.f;
#pragma unroll
        for (int nb = 0; nb < NB; nb++) {
            float x = sx0[nb][u];
            au0[nb] += x * w0;
            as0[nb] += x * ws;
            ad[nb] += x * wd;
        }
    }
#pragma unroll
    for (int nb = 0; nb < NB; nb++) {
        int n = n0 + nb;
        g_u0[n * CC + v] = au0[nb] * inv_c;
        out[SC_OFF + (size_t)n * 512 + v] = as0[nb] * inv_c;
        if (v < DD) g_down[n * DD + v] = ad[nb] * inv_c;
    }

    float au1[NB][3], as1[NB][3];
#pragma unroll
    for (int nb = 0; nb < NB; nb++)
#pragma unroll
        for (int i = 0; i < 3; i++) { au1[nb][i] = 0.f; as1[nb][i] = 0.f; }
    for (int u = 0; u < CC; u++) {
        float wu = Wu1[u * CC + v];
        float ws = Ws1[u * CC + v];
#pragma unroll
        for (int nb = 0; nb < NB; nb++) {
#pragma unroll
            for (int i = 0; i < 3; i++) {
                float x = sx1[nb][u * 3 + i];
                au1[nb][i] += x * wu;
                as1[nb][i] += x * ws;
            }
        }
    }
#pragma unroll
    for (int nb = 0; nb < NB; nb++) {
        int n = n0 + nb;
#pragma unroll
        for (int i = 0; i < 3; i++) {
            g_u1[n * (CC * 3) + v * 3 + i] = au1[nb][i] * inv_c;
            out[SC_OFF + (size_t)n * 512 + 128 + v * 3 + i] = as1[nb][i] * inv_c;
        }
    }
}

// ---------------------------------------------------------------------------
// A-row element fetch (one float4), templated on source.
// SRC 0: gathered row [edge_feats(8) | down[sender](64) | down[receiver](64)]
// SRC 1/2: dense g_hA / g_hB
// ---------------------------------------------------------------------------
template <int SRC>
__device__ __forceinline__ float4 load_a_f4(const float* __restrict__ A,
                                            int row, int k0, int K,
                                            const float* __restrict__ edge_feats,
                                            const int* __restrict__ edge_index) {
    float4 v = make_float4(0.f, 0.f, 0.f, 0.f);
    if (k0 < K) {  // K % 4 == 0 and all segment boundaries are 4-aligned
        if (SRC == 0) {
            if (k0 < 8) {
                v = *(const float4*)(edge_feats + (size_t)row * 8 + k0);
            } else if (k0 < 72) {
                int s = edge_index[row];
                v = *(const float4*)(g_down + (size_t)s * DD + (k0 - 8));
            } else {
                int r = edge_index[NE + row];
                v = *(const float4*)(g_down + (size_t)r * DD + (k0 - 72));
            }
        } else {
            v = *(const float4*)(A + (size_t)row * K + k0);
        }
    }
    return v;
}

// ---------------------------------------------------------------------------
// SGEMM: C[M,Nc] = act( A[M,K] @ B[K,Nc] * scale )
// BM=BN=128, BK=16, 256 threads, 8x8 microtile, double-buffered smem.
// Per k-step: 4x LDS.128 feed 64 FFMA  (4 FFMA / smem float).
// ---------------------------------------------------------------------------
template <int SRC, int DST, bool SILU>
__global__ void __launch_bounds__(256, 1)
mlp_gemm(const float* __restrict__ B,
         int Nc, int K, float scale,
         const float* __restrict__ edge_feats,
         const int* __restrict__ edge_index) {
    const float* A = (SRC == 1) ? g_hA : (SRC == 2) ? g_hB : nullptr;
    float* Cout = (DST == 1) ? g_hA : (DST == 2) ? g_hB : g_tpw;

    __shared__ float As[2][16][132];  // +4 pad: reduces STS bank conflicts, keeps 16B align
    __shared__ float Bs[2][16][128];

    int tid = threadIdx.x;           // 0..255
    int tx = tid & 15;               // col group (0..15)
    int ty = tid >> 4;               // row group (0..15)
    int rowBase = blockIdx.y * 128;
    int colBase = blockIdx.x * 128;

    // A gmem mapping: 128 rows x 16 k = 512 float4; thread handles l=tid, l=tid+256
    int aRow = tid >> 2;             // 0..63  (second load: +64)
    int aK4 = (tid & 3) * 4;         // 0,4,8,12
    // B gmem mapping: 16 k x 128 n = 512 float4; l=tid, l=tid+256
    int bK = tid >> 5;               // 0..7   (second load: +8)
    int bN4 = (tid & 31) * 4;        // 0..124

    float acc[8][8];
#pragma unroll
    for (int i = 0; i < 8; i++)
#pragma unroll
        for (int j = 0; j < 8; j++) acc[i][j] = 0.f;

    float4 aR0, aR1, bR0, bR1;

    int kTiles = (K + 15) >> 4;

    // ---- preload tile 0 ----
    aR0 = load_a_f4<SRC>(A, rowBase + aRow, aK4, K, edge_feats, edge_index);
    aR1 = load_a_f4<SRC>(A, rowBase + aRow + 64, aK4, K, edge_feats, edge_index);
    {
        int kk = bK;
        bR0 = (kk < K) ? *(const float4*)(B + (size_t)kk * Nc + colBase + bN4)
                       : make_float4(0.f, 0.f, 0.f, 0.f);
        kk = bK + 8;
        bR1 = (kk < K) ? *(const float4*)(B + (size_t)kk * Nc + colBase + bN4)
                       : make_float4(0.f, 0.f, 0.f, 0.f);
    }
    // store tile 0 into buf 0 (A transposed: As[k][row])
    As[0][aK4 + 0][aRow] = aR0.x; As[0][aK4 + 1][aRow] = aR0.y;
    As[0][aK4 + 2][aRow] = aR0.z; As[0][aK4 + 3][aRow] = aR0.w;
    As[0][aK4 + 0][aRow + 64] = aR1.x; As[0][aK4 + 1][aRow + 64] = aR1.y;
    As[0][aK4 + 2][aRow + 64] = aR1.z; As[0][aK4 + 3][aRow + 64] = aR1.w;
    *(float4*)&Bs[0][bK][bN4] = bR0;
    *(float4*)&Bs[0][bK + 8][bN4] = bR1;
    __syncthreads();

    for (int kt = 0; kt < kTiles; kt++) {
        int cur = kt & 1;
        // prefetch next tile into registers
        if (kt + 1 < kTiles) {
            int kb = (kt + 1) * 16;
            aR0 = load_a_f4<SRC>(A, rowBase + aRow, kb + aK4, K, edge_feats, edge_index);
            aR1 = load_a_f4<SRC>(A, rowBase + aRow + 64, kb + aK4, K, edge_feats, edge_index);
            int kk = kb + bK;
            bR0 = (kk < K) ? *(const float4*)(B + (size_t)kk * Nc + colBase + bN4)
                           : make_float4(0.f, 0.f, 0.f, 0.f);
            kk = kb + bK + 8;
            bR1 = (kk < K) ? *(const float4*)(B + (size_t)kk * Nc + colBase + bN4)
                           : make_float4(0.f, 0.f, 0.f, 0.f);
        }

        // compute from buf cur
#pragma unroll
        for (int k = 0; k < 16; k++) {
            float4 a0 = *(const float4*)&As[cur][k][ty * 4];
            float4 a1 = *(const float4*)&As[cur][k][64 + ty * 4];
            float4 b0 = *(const float4*)&Bs[cur][k][tx * 4];
            float4 b1 = *(const float4*)&Bs[cur][k][64 + tx * 4];
            float a[8] = {a0.x, a0.y, a0.z, a0.w, a1.x, a1.y, a1.z, a1.w};
            float b[8] = {b0.x, b0.y, b0.z, b0.w, b1.x, b1.y, b1.z, b1.w};
#pragma unroll
            for (int i = 0; i < 8; i++)
#pragma unroll
                for (int j = 0; j < 8; j++) acc[i][j] += a[i] * b[j];
        }

        // commit next tile to the other buffer (no one reads it concurrently)
        if (kt + 1 < kTiles) {
            int nxt = cur ^ 1;
            As[nxt][aK4 + 0][aRow] = aR0.x; As[nxt][aK4 + 1][aRow] = aR0.y;
            As[nxt][aK4 + 2][aRow] = aR0.z; As[nxt][aK4 + 3][aRow] = aR0.w;
            As[nxt][aK4 + 0][aRow + 64] = aR1.x; As[nxt][aK4 + 1][aRow + 64] = aR1.y;
            As[nxt][aK4 + 2][aRow + 64] = aR1.z; As[nxt][aK4 + 3][aRow + 64] = aR1.w;
            *(float4*)&Bs[nxt][bK][bN4] = bR0;
            *(float4*)&Bs[nxt][bK + 8][bN4] = bR1;
            __syncthreads();
        }
    }

    // ---- epilogue ----
#pragma unroll
    for (int mi = 0; mi < 2; mi++) {
#pragma unroll
        for (int m = 0; m < 4; m++) {
            int row = rowBase + mi * 64 + ty * 4 + m;
#pragma unroll
            for (int ni = 0; ni < 2; ni++) {
                float r[4];
#pragma unroll
                for (int n = 0; n < 4; n++) {
                    float x = acc[mi * 4 + m][ni * 4 + n] * scale;
                    if (SILU) x = x / (1.0f + expf(-x));
                    r[n] = x;
                }
                float4 v = make_float4(r[0], r[1], r[2], r[3]);
                *(float4*)(Cout + (size_t)row * Nc + colBase + ni * 64 + tx * 4) = v;
            }
        }
    }
}

// ---------------------------------------------------------------------------
// Edge tensor product + scatter-add (segment_sum) into g_m
// ---------------------------------------------------------------------------
__global__ void edge_tp_kernel(const float* __restrict__ edge_attrs,
                               const int* __restrict__ edge_index) {
    int e = blockIdx.x;
    int c = threadIdx.x;

    int s = edge_index[e];
    int r = edge_index[NE + e];
    float y0 = edge_attrs[(size_t)e * 4 + 0];
    float y1x = edge_attrs[(size_t)e * 4 + 1];
    float y1y = edge_attrs[(size_t)e * 4 + 2];
    float y1z = edge_attrs[(size_t)e * 4 + 3];

    const float* tw = g_tpw + (size_t)e * TPWN;
    float w0 = tw[c];
    float w1 = tw[128 + c];
    float w2 = tw[256 + c];
    float w3 = tw[384 + c];

    float xs0 = g_u0[(size_t)s * CC + c];
    const float* u1p = g_u1 + (size_t)s * (CC * 3) + c * 3;
    float x1a = u1p[0], x1b = u1p[1], x1c = u1p[2];

    float* mrow = g_m + (size_t)r * MROW;
    const float rsqrt3 = 0.5773502691896258f;

    atomicAdd(mrow + c, w0 * xs0 * y0);
    float dot = x1a * y1x + x1b * y1y + x1c * y1z;
    atomicAdd(mrow + 128 + c, w3 * dot * rsqrt3);
    float a = w1 * xs0;
    atomicAdd(mrow + 256 + c * 3 + 0, a * y1x);
    atomicAdd(mrow + 256 + c * 3 + 1, a * y1y);
    atomicAdd(mrow + 256 + c * 3 + 2, a * y1z);
    float b = w2 * y0;
    atomicAdd(mrow + 256 + (128 + c) * 3 + 0, b * x1a);
    atomicAdd(mrow + 256 + (128 + c) * 3 + 1, b * x1b);
    atomicAdd(mrow + 256 + (128 + c) * 3 + 2, b * x1c);
}

// ---------------------------------------------------------------------------
// Final linear: message[n,v,0] = (m0 @ Wl0)/256 ; message[n,v,1..3] = (m1 @ Wl1)/256
// ---------------------------------------------------------------------------
__global__ void msg_kernel(const float* __restrict__ Wl0,
                           const float* __restrict__ Wl1,
                           float* __restrict__ out) {
    const int NB = 8;
    __shared__ float sm[NB][MROW];
    int n0 = blockIdx.x * NB;
    int v = threadIdx.x;

    for (int j = v; j < NB * MROW; j += 128) {
        sm[j >> 10][j & 1023] = g_m[(size_t)n0 * MROW + j];
    }
    __syncthreads();

    float m0acc[NB];
    float m1acc[NB][3];
#pragma unroll
    for (int nb = 0; nb < NB; nb++) {
        m0acc[nb] = 0.f;
#pragma unroll
        for (int i = 0; i < 3; i++) m1acc[nb][i] = 0.f;
    }

    for (int cc = 0; cc < 256; cc++) {
        float w0 = Wl0[cc * 128 + v];
        float w1 = Wl1[cc * 128 + v];
#pragma unroll
        for (int nb = 0; nb < NB; nb++) {
            m0acc[nb] += sm[nb][cc] * w0;
#pragma unroll
            for (int i = 0; i < 3; i++)
                m1acc[nb][i] += sm[nb][256 + cc * 3 + i] * w1;
        }
    }

    const float sc = 1.0f / 256.0f;  // (1/sqrt(256)) / AVG_NEIGH
#pragma unroll
    for (int nb = 0; nb < NB; nb++) {
        int n = n0 + nb;
        float4 v4;
        v4.x = m0acc[nb] * sc;
        v4.y = m1acc[nb][0] * sc;
        v4.z = m1acc[nb][1] * sc;
        v4.w = m1acc[nb][2] * sc;
        *(float4*)(out + (size_t)n * 512 + v * 4) = v4;
    }
}

// ---------------------------------------------------------------------------
extern "C" void kernel_launch(void* const* d_in, const int* in_sizes, int n_in,
                              void* d_out, int out_size) {
    const float* node_feats = (const float*)d_in[1];
    const float* edge_attrs = (const float*)d_in[2];
    const float* edge_feats = (const float*)d_in[3];
    const int*   edge_index = (const int*)d_in[4];
    const float* W_up0  = (const float*)d_in[5];
    const float* W_up1  = (const float*)d_in[6];
    const float* W_down = (const float*)d_in[7];
    const float* mlp_w1 = (const float*)d_in[8];
    const float* mlp_w2 = (const float*)d_in[9];
    const float* mlp_w3 = (const float*)d_in[10];
    const float* mlp_w4 = (const float*)d_in[11];
    const float* W_lin0 = (const float*)d_in[12];
    const float* W_lin1 = (const float*)d_in[13];
    const float* W_skip0 = (const float*)d_in[14];
    const float* W_skip1 = (const float*)d_in[15];
    float* out = (float*)d_out;

    // 1) zero the segment-sum accumulator
    zero_m_kernel<<<512, 256>>>();

    // 2) node transforms (+ writes sc part of output)
    node_kernel<<<NN / 8, 128>>>(node_feats, W_up0, W_up1, W_down, W_skip0, W_skip1, out);

    // 3) edge MLP: 4 GEMMs over E=160000 rows (scratch resolved device-side)
    float scale1 = 1.0f / sqrtf(136.0f);
    float scale2 = 1.0f / 16.0f;

    {
        dim3 grid(HID / 128, NE / 128);  // (2, 1250)
        mlp_gemm<0, 1, true><<<grid, 256>>>(mlp_w1, HID, KAUG, scale1,
                                            edge_feats, edge_index);
        mlp_gemm<1, 2, true><<<grid, 256>>>(mlp_w2, HID, HID, scale2,
                                            nullptr, nullptr);
        mlp_gemm<2, 1, true><<<grid, 256>>>(mlp_w3, HID, HID, scale2,
                                            nullptr, nullptr);
    }
    {
        dim3 grid(TPWN / 128, NE / 128);  // (4, 1250)
        mlp_gemm<1, 3, false><<<grid, 256>>>(mlp_w4, TPWN, HID, scale2,
                                             nullptr, nullptr);
    }

    // 4) edge tensor product + scatter
    edge_tp_kernel<<<NE, 128>>>(edge_attrs, edge_index);

    // 5) final linear -> message part of output
    msg_kernel<<<NN / 8, 128>>>(W_lin0, W_lin1, out);

    (void)in_sizes; (void)n_in; (void)out_size;
}

// round 11
// speedup vs baseline: 2.8601x; 1.5025x over previous
#include <cuda_runtime.h>
#include <cuda_bf16.h>
#include <math.h>
#include <stdint.h>

#define NN 10000
#define NE 160000
#define CC 128
#define DD 64
#define HID 256
#define TPWN 512
#define MROW 1024          // m0 (256) + m1 (256*3)
#define SC_OFF (NN * 512)  // message is N*128*4 = N*512 floats, sc follows

#define KP1 448            // layer-1 K': [hi 136+8pad | lo 136+8pad | hi 136+8pad | 16 pad]
#define KPH 768            // hidden K': [hi 256 | lo 256 | hi 256]

// -------- device scratch (allocation-free rule: static __device__ globals) ----
// Only referenced from device code (host-side use binds the host shadow; round-5 bug).
__device__ float g_u0[NN * CC];
__device__ float g_u1[NN * CC * 3];
__device__ float g_down[NN * DD];
__device__ float g_tpw[NE * TPWN];
__device__ float g_m[NN * MROW];

__device__ __align__(16) __nv_bfloat16 g_aug[(size_t)NE * KP1];   // layer-1 A (split, padded)
__device__ __align__(16) __nv_bfloat16 g_act0[(size_t)NE * KPH];  // activation ping [hi|lo|hi]
__device__ __align__(16) __nv_bfloat16 g_act1[(size_t)NE * KPH];  // activation pong
__device__ __align__(16) __nv_bfloat16 g_w1T[HID * KP1];          // W1^T split [256][448]
__device__ __align__(16) __nv_bfloat16 g_w2T[HID * KPH];          // [256][768] [hi|hi|lo]
__device__ __align__(16) __nv_bfloat16 g_w3T[HID * KPH];
__device__ __align__(16) __nv_bfloat16 g_w4T[TPWN * KPH];         // [512][768]

// ======================= warp-MMA helpers (sm_80+ ISA only) =================
__device__ __forceinline__ uint32_t smem_u32(const void* p) {
    uint32_t a;
    asm("{ .reg .u64 t; cvta.to.shared.u64 t, %1; cvt.u32.u64 %0, t; }" : "=r"(a) : "l"(p));
    return a;
}
#define SW128(off) ((off) ^ (((off) >> 3) & 0x70))

__device__ __forceinline__ void ldm_x4(uint32_t* r, uint32_t addr) {
    asm volatile("ldmatrix.sync.aligned.m8n8.x4.shared.b16 {%0,%1,%2,%3}, [%4];"
                 : "=r"(r[0]), "=r"(r[1]), "=r"(r[2]), "=r"(r[3]) : "r"(addr));
}
__device__ __forceinline__ void mma16816(float* c, const uint32_t* a, const uint32_t* b) {
    asm volatile(
        "mma.sync.aligned.m16n8k16.row.col.f32.bf16.bf16.f32 "
        "{%0,%1,%2,%3}, {%4,%5,%6,%7}, {%8,%9}, {%0,%1,%2,%3};"
        : "+f"(c[0]), "+f"(c[1]), "+f"(c[2]), "+f"(c[3])
        : "r"(a[0]), "r"(a[1]), "r"(a[2]), "r"(a[3]), "r"(b[0]), "r"(b[1]));
}

// ---------------------------------------------------------------------------
// zero the segment-sum accumulator (must run every launch: deterministic)
// ---------------------------------------------------------------------------
__global__ void zero_m_kernel() {
    int idx = blockIdx.x * blockDim.x + threadIdx.x;
    int stride = gridDim.x * blockDim.x;
    for (int i = idx; i < NN * MROW; i += stride) g_m[i] = 0.0f;
}

// ---------------------------------------------------------------------------
// Node transforms: u0, u1, down (to scratch) + sc (directly to output)
// ---------------------------------------------------------------------------
__global__ void node_kernel(const float* __restrict__ nf,
                            const float* __restrict__ Wu0,
                            const float* __restrict__ Wu1,
                            const float* __restrict__ Wd,
                            const float* __restrict__ Ws0,
                            const float* __restrict__ Ws1,
                            float* __restrict__ out) {
    const int NB = 8;
    __shared__ float sx0[NB][CC];
    __shared__ float sx1[NB][CC * 3];
    int n0 = blockIdx.x * NB;
    int v = threadIdx.x;  // 0..127

    for (int j = v; j < NB * 512; j += 128) {
        int nb = j >> 9;
        int k = j & 511;
        float val = nf[(size_t)(n0 + nb) * 512 + k];
        if (k < 128) sx0[nb][k] = val;
        else sx1[nb][k - 128] = val;
    }
    __syncthreads();

    const float inv_c = 0.08838834764831845f;  // 1/sqrt(128)

    float au0[NB], as0[NB], ad[NB];
#pragma unroll
    for (int nb = 0; nb < NB; nb++) { au0[nb] = 0.f; as0[nb] = 0.f; ad[nb] = 0.f; }
    for (int u = 0; u < CC; u++) {
        float w0 = Wu0[u * CC + v];
        float ws = Ws0[u * CC + v];
        float wd = (v < DD) ? Wd[u * DD + v] : 0.f;
#pragma unroll
        for (int nb = 0; nb < NB; nb++) {
            float x = sx0[nb][u];
            au0[nb] += x * w0;
            as0[nb] += x * ws;
            ad[nb] += x * wd;
        }
    }
#pragma unroll
    for (int nb = 0; nb < NB; nb++) {
        int n = n0 + nb;
        g_u0[n * CC + v] = au0[nb] * inv_c;
        out[SC_OFF + (size_t)n * 512 + v] = as0[nb] * inv_c;
        if (v < DD) g_down[n * DD + v] = ad[nb] * inv_c;
    }

    float au1[NB][3], as1[NB][3];
#pragma unroll
    for (int nb = 0; nb < NB; nb++)
#pragma unroll
        for (int i = 0; i < 3; i++) { au1[nb][i] = 0.f; as1[nb][i] = 0.f; }
    for (int u = 0; u < CC; u++) {
        float wu = Wu1[u * CC + v];
        float ws = Ws1[u * CC + v];
#pragma unroll
        for (int nb = 0; nb < NB; nb++) {
#pragma unroll
            for (int i = 0; i < 3; i++) {
                float x = sx1[nb][u * 3 + i];
                au1[nb][i] += x * wu;
                as1[nb][i] += x * ws;
            }
        }
    }
#pragma unroll
    for (int nb = 0; nb < NB; nb++) {
        int n = n0 + nb;
#pragma unroll
        for (int i = 0; i < 3; i++) {
            g_u1[n * (CC * 3) + v * 3 + i] = au1[nb][i] * inv_c;
            out[SC_OFF + (size_t)n * 512 + 128 + v * 3 + i] = as1[nb][i] * inv_c;
        }
    }
}

// ---------------------------------------------------------------------------
// Weight prep: transpose to [N][K'] K-major bf16 with [hi|hi|lo] split.
// ---------------------------------------------------------------------------
__global__ void prep_w1(const float* __restrict__ w) {  // [136][256] -> g_w1T [256][448]
    int i = blockIdx.x * blockDim.x + threadIdx.x;
    if (i >= HID * KP1) return;
    int n = i / KP1, k = i % KP1;
    __nv_bfloat16 o = __float2bfloat16(0.f);
    if (k < 432) {
        int seg = k / 144, rem = k % 144;
        if (rem < 136) {
            float v = w[rem * HID + n];
            __nv_bfloat16 h = __float2bfloat16(v);
            o = (seg < 2) ? h : __float2bfloat16(v - __bfloat162float(h));
        }
    }
    g_w1T[n * KP1 + k] = o;
}

template <int WSEL>  // 2,3,4
__global__ void prep_w_hid(const float* __restrict__ w, int Nc) {
    int i = blockIdx.x * blockDim.x + threadIdx.x;
    if (i >= Nc * KPH) return;
    int n = i / KPH, k = i % KPH;
    int seg = k >> 8, rem = k & 255;
    float v = w[rem * Nc + n];
    __nv_bfloat16 h = __float2bfloat16(v);
    __nv_bfloat16 o = (seg < 2) ? h : __float2bfloat16(v - __bfloat162float(h));
    __nv_bfloat16* dst = (WSEL == 2) ? g_w2T : (WSEL == 3) ? g_w3T : g_w4T;
    dst[(size_t)n * KPH + k] = o;
}

// ---------------------------------------------------------------------------
// Build layer-1 A operand: [hi(aug) 144 | lo(aug) 144 | hi(aug) 144 | 16 pad]
// aug = [edge_feats(8) | down[sender](64) | down[receiver](64)] padded to 144.
// ---------------------------------------------------------------------------
__global__ void prep_aug(const float* __restrict__ ef, const int* __restrict__ eidx) {
    int i = blockIdx.x * blockDim.x + threadIdx.x;
    if (i >= NE * 160) return;
    int e = i / 160, j = i % 160;
    size_t base = (size_t)e * KP1;
    if (j < 144) {
        float v = 0.f;
        if (j < 8) v = ef[(size_t)e * 8 + j];
        else if (j < 72) v = g_down[(size_t)eidx[e] * DD + (j - 8)];
        else if (j < 136) v = g_down[(size_t)eidx[NE + e] * DD + (j - 72)];
        __nv_bfloat16 h = __float2bfloat16(v);
        __nv_bfloat16 l = __float2bfloat16(v - __bfloat162float(h));
        g_aug[base + j] = h;
        g_aug[base + 144 + j] = l;
        g_aug[base + 288 + j] = h;
    } else {
        g_aug[base + 432 + (j - 144)] = __float2bfloat16(0.f);
    }
}

// ---------------------------------------------------------------------------
// HMMA GEMM: C[128 x 128 tile] = A'[M,K'] @ W'[N,K']^T, fp32 accum.
// 8 warps: 4(M) x 2(N) -> warp tile 32x64. mma.m16n8k16 bf16, ldmatrix feeds.
// K staged 64 bf16 (128B SW128 rows), double-buffered, gmem->reg prefetch.
// DST: 0/1 -> silu + bf16 hi/lo split into g_act0/g_act1; 2 -> fp32 g_tpw.
// ---------------------------------------------------------------------------
template <int SRC, int WSEL, int DST, int KPRM, bool SILU>
__global__ void __launch_bounds__(256)
mma_gemm(float scale) {
    const __nv_bfloat16* __restrict__ A =
        (SRC == 0) ? g_aug : (SRC == 1) ? g_act0 : g_act1;
    const __nv_bfloat16* __restrict__ W =
        (WSEL == 1) ? g_w1T : (WSEL == 2) ? g_w2T : (WSEL == 3) ? g_w3T : g_w4T;

    extern __shared__ char smem[];
    const int BOFF = 32768;  // A: 2 x 16KB, B: 2 x 16KB
    uint32_t sb = smem_u32(smem);

    int tid = threadIdx.x;
    int lane = tid & 31, wid = tid >> 5;
    int wm = wid & 3;        // 0..3 -> M offset wm*32
    int wn = wid >> 2;       // 0..1 -> N offset wn*64
    int rowBase = blockIdx.y * 128;
    int colBase = blockIdx.x * 128;
    const int S = KPRM / 64;

    const __nv_bfloat16* Ag0 = A + (size_t)rowBase * KPRM;
    const __nv_bfloat16* Bg0 = W + (size_t)colBase * KPRM;

    float acc[2][8][4];
#pragma unroll
    for (int i = 0; i < 2; i++)
#pragma unroll
        for (int j = 0; j < 8; j++)
#pragma unroll
            for (int q = 0; q < 4; q++) acc[i][j][q] = 0.f;

    uint4 ar[4], br[4];
    auto fetch = [&](int ks) {
#pragma unroll
        for (int c = 0; c < 4; c++) {
            int idx = tid + c * 256;           // 0..1023
            int row = idx >> 3, cb = idx & 7;  // 128 rows x 8 chunks of 8 bf16
            ar[c] = *(const uint4*)(Ag0 + (size_t)row * KPRM + ks * 64 + cb * 8);
            br[c] = *(const uint4*)(Bg0 + (size_t)row * KPRM + ks * 64 + cb * 8);
        }
    };
    auto commit = [&](int buf) {
        char* as = smem + buf * 16384;
        char* bs = smem + BOFF + buf * 16384;
#pragma unroll
        for (int c = 0; c < 4; c++) {
            int idx = tid + c * 256;
            int row = idx >> 3, cb = idx & 7;
            uint32_t so = SW128((uint32_t)(row * 128 + cb * 16));
            *(uint4*)(as + so) = ar[c];
            *(uint4*)(bs + so) = br[c];
        }
    };

    fetch(0); commit(0);
    __syncthreads();

    for (int s = 0; s < S; s++) {
        int cur = s & 1;
        if (s + 1 < S) fetch(s + 1);

        uint32_t aBase = sb + cur * 16384;
        uint32_t bBase = sb + BOFF + cur * 16384;
#pragma unroll
        for (int k16 = 0; k16 < 4; k16++) {
            uint32_t a[2][4];
#pragma unroll
            for (int mf = 0; mf < 2; mf++) {
                int r = wm * 32 + mf * 16 + (lane & 15);
                int kc = k16 * 16 + ((lane >> 4) << 3);
                ldm_x4(a[mf], aBase + SW128((uint32_t)(r * 128 + kc * 2)));
            }
            uint32_t b[8][2];
#pragma unroll
            for (int g = 0; g < 4; g++) {
                int nr = wn * 64 + g * 16 + (lane & 7) + ((lane >> 4) & 1) * 8;
                int kc = k16 * 16 + (((lane >> 3) & 1) << 3);
                uint32_t t4[4];
                ldm_x4(t4, bBase + SW128((uint32_t)(nr * 128 + kc * 2)));
                b[2 * g][0] = t4[0]; b[2 * g][1] = t4[1];
                b[2 * g + 1][0] = t4[2]; b[2 * g + 1][1] = t4[3];
            }
#pragma unroll
            for (int mf = 0; mf < 2; mf++)
#pragma unroll
                for (int nf = 0; nf < 8; nf++)
                    mma16816(acc[mf][nf], a[mf], b[nf]);
        }

        if (s + 1 < S) commit(cur ^ 1);
        __syncthreads();
    }

    // ---- epilogue: frag (mf,nf): rows r0,r0+8; cols c0,c0+1 ----
#pragma unroll
    for (int mf = 0; mf < 2; mf++) {
#pragma unroll
        for (int nf = 0; nf < 8; nf++) {
            int r0 = rowBase + wm * 32 + mf * 16 + (lane >> 2);
            int c0 = colBase + wn * 64 + nf * 8 + (lane & 3) * 2;
            if (DST == 2) {
                float2 v0 = make_float2(acc[mf][nf][0] * scale, acc[mf][nf][1] * scale);
                float2 v1 = make_float2(acc[mf][nf][2] * scale, acc[mf][nf][3] * scale);
                *(float2*)(g_tpw + (size_t)r0 * TPWN + c0) = v0;
                *(float2*)(g_tpw + (size_t)(r0 + 8) * TPWN + c0) = v1;
            } else {
                __nv_bfloat16* dst = (DST == 0) ? g_act0 : g_act1;
#pragma unroll
                for (int rr = 0; rr < 2; rr++) {
                    float x0 = acc[mf][nf][rr * 2 + 0] * scale;
                    float x1 = acc[mf][nf][rr * 2 + 1] * scale;
                    if (SILU) {
                        x0 = x0 / (1.0f + expf(-x0));
                        x1 = x1 / (1.0f + expf(-x1));
                    }
                    __nv_bfloat16 h0 = __float2bfloat16(x0);
                    __nv_bfloat16 h1 = __float2bfloat16(x1);
                    __nv_bfloat16 l0 = __float2bfloat16(x0 - __bfloat162float(h0));
                    __nv_bfloat16 l1 = __float2bfloat16(x1 - __bfloat162float(h1));
                    __nv_bfloat162 hp; hp.x = h0; hp.y = h1;
                    __nv_bfloat162 lp; lp.x = l0; lp.y = l1;
                    __nv_bfloat16* p = dst + (size_t)(r0 + rr * 8) * KPH + c0;
                    *(__nv_bfloat162*)(p) = hp;          // hi segment
                    *(__nv_bfloat162*)(p + 256) = lp;    // lo segment
                    *(__nv_bfloat162*)(p + 512) = hp;    // hi copy
                }
            }
        }
    }
}

// ---------------------------------------------------------------------------
// Edge tensor product + scatter-add (segment_sum) into g_m
// ---------------------------------------------------------------------------
__global__ void edge_tp_kernel(const float* __restrict__ edge_attrs,
                               const int* __restrict__ edge_index) {
    int e = blockIdx.x;
    int c = threadIdx.x;

    int s = edge_index[e];
    int r = edge_index[NE + e];
    float y0 = edge_attrs[(size_t)e * 4 + 0];
    float y1x = edge_attrs[(size_t)e * 4 + 1];
    float y1y = edge_attrs[(size_t)e * 4 + 2];
    float y1z = edge_attrs[(size_t)e * 4 + 3];

    const float* tw = g_tpw + (size_t)e * TPWN;
    float w0 = tw[c];
    float w1 = tw[128 + c];
    float w2 = tw[256 + c];
    float w3 = tw[384 + c];

    float xs0 = g_u0[(size_t)s * CC + c];
    const float* u1p = g_u1 + (size_t)s * (CC * 3) + c * 3;
    float x1a = u1p[0], x1b = u1p[1], x1c = u1p[2];

    float* mrow = g_m + (size_t)r * MROW;
    const float rsqrt3 = 0.5773502691896258f;

    atomicAdd(mrow + c, w0 * xs0 * y0);
    float dot = x1a * y1x + x1b * y1y + x1c * y1z;
    atomicAdd(mrow + 128 + c, w3 * dot * rsqrt3);
    float a = w1 * xs0;
    atomicAdd(mrow + 256 + c * 3 + 0, a * y1x);
    atomicAdd(mrow + 256 + c * 3 + 1, a * y1y);
    atomicAdd(mrow + 256 + c * 3 + 2, a * y1z);
    float b = w2 * y0;
    atomicAdd(mrow + 256 + (128 + c) * 3 + 0, b * x1a);
    atomicAdd(mrow + 256 + (128 + c) * 3 + 1, b * x1b);
    atomicAdd(mrow + 256 + (128 + c) * 3 + 2, b * x1c);
}

// ---------------------------------------------------------------------------
// Final linear: message[n,v,0] = (m0 @ Wl0)/256 ; message[n,v,1..3] = (m1 @ Wl1)/256
// ---------------------------------------------------------------------------
__global__ void msg_kernel(const float* __restrict__ Wl0,
                           const float* __restrict__ Wl1,
                           float* __restrict__ out) {
    const int NB = 8;
    __shared__ float sm[NB][MROW];
    int n0 = blockIdx.x * NB;
    int v = threadIdx.x;

    for (int j = v; j < NB * MROW; j += 128) {
        sm[j >> 10][j & 1023] = g_m[(size_t)n0 * MROW + j];
    }
    __syncthreads();

    float m0acc[NB];
    float m1acc[NB][3];
#pragma unroll
    for (int nb = 0; nb < NB; nb++) {
        m0acc[nb] = 0.f;
#pragma unroll
        for (int i = 0; i < 3; i++) m1acc[nb][i] = 0.f;
    }

    for (int cc = 0; cc < 256; cc++) {
        float w0 = Wl0[cc * 128 + v];
        float w1 = Wl1[cc * 128 + v];
#pragma unroll
        for (int nb = 0; nb < NB; nb++) {
            m0acc[nb] += sm[nb][cc] * w0;
#pragma unroll
            for (int i = 0; i < 3; i++)
                m1acc[nb][i] += sm[nb][256 + cc * 3 + i] * w1;
        }
    }

    const float sc = 1.0f / 256.0f;  // (1/sqrt(256)) / AVG_NEIGH
#pragma unroll
    for (int nb = 0; nb < NB; nb++) {
        int n = n0 + nb;
        float4 v4;
        v4.x = m0acc[nb] * sc;
        v4.y = m1acc[nb][0] * sc;
        v4.z = m1acc[nb][1] * sc;
        v4.w = m1acc[nb][2] * sc;
        *(float4*)(out + (size_t)n * 512 + v * 4) = v4;
    }
}

// ---------------------------------------------------------------------------
extern "C" void kernel_launch(void* const* d_in, const int* in_sizes, int n_in,
                              void* d_out, int out_size) {
    const float* node_feats = (const float*)d_in[1];
    const float* edge_attrs = (const float*)d_in[2];
    const float* edge_feats = (const float*)d_in[3];
    const int*   edge_index = (const int*)d_in[4];
    const float* W_up0  = (const float*)d_in[5];
    const float* W_up1  = (const float*)d_in[6];
    const float* W_down = (const float*)d_in[7];
    const float* mlp_w1 = (const float*)d_in[8];
    const float* mlp_w2 = (const float*)d_in[9];
    const float* mlp_w3 = (const float*)d_in[10];
    const float* mlp_w4 = (const float*)d_in[11];
    const float* W_lin0 = (const float*)d_in[12];
    const float* W_lin1 = (const float*)d_in[13];
    const float* W_skip0 = (const float*)d_in[14];
    const float* W_skip1 = (const float*)d_in[15];
    float* out = (float*)d_out;

    const int MM_SMEM = 65536;  // 2x16KB A + 2x16KB B
    cudaFuncSetAttribute(mma_gemm<0, 1, 0, KP1, true>,
                         cudaFuncAttributeMaxDynamicSharedMemorySize, MM_SMEM);
    cudaFuncSetAttribute(mma_gemm<1, 2, 1, KPH, true>,
                         cudaFuncAttributeMaxDynamicSharedMemorySize, MM_SMEM);
    cudaFuncSetAttribute(mma_gemm<2, 3, 0, KPH, true>,
                         cudaFuncAttributeMaxDynamicSharedMemorySize, MM_SMEM);
    cudaFuncSetAttribute(mma_gemm<1, 4, 2, KPH, false>,
                         cudaFuncAttributeMaxDynamicSharedMemorySize, MM_SMEM);

    // 1) zero segment-sum accumulator
    zero_m_kernel<<<512, 256>>>();

    // 2) node transforms (+ sc output); produces g_down for prep_aug
    node_kernel<<<NN / 8, 128>>>(node_feats, W_up0, W_up1, W_down, W_skip0, W_skip1, out);

    // 3) weight prep (transpose + bf16 hi/lo split)
    prep_w1<<<(HID * KP1 + 255) / 256, 256>>>(mlp_w1);
    prep_w_hid<2><<<(HID * KPH + 255) / 256, 256>>>(mlp_w2, HID);
    prep_w_hid<3><<<(HID * KPH + 255) / 256, 256>>>(mlp_w3, HID);
    prep_w_hid<4><<<(TPWN * KPH + 255) / 256, 256>>>(mlp_w4, TPWN);

    // 4) layer-1 A operand (gather + split + pad)
    prep_aug<<<(NE * 160 + 255) / 256, 256>>>(edge_feats, edge_index);

    // 5) edge MLP on HMMA tensor cores (fp32-accurate via 3-term bf16 split)
    float scale1 = 1.0f / sqrtf(136.0f);
    float scale2 = 1.0f / 16.0f;
    {
        dim3 g(HID / 128, NE / 128);   // (2, 1250)
        mma_gemm<0, 1, 0, KP1, true><<<g, 256, MM_SMEM>>>(scale1);   // aug  -> act0
        mma_gemm<1, 2, 1, KPH, true><<<g, 256, MM_SMEM>>>(scale2);   // act0 -> act1
        mma_gemm<2, 3, 0, KPH, true><<<g, 256, MM_SMEM>>>(scale2);   // act1 -> act0
    }
    {
        dim3 g(TPWN / 128, NE / 128);  // (4, 1250)
        mma_gemm<1, 4, 2, KPH, false><<<g, 256, MM_SMEM>>>(scale2);  // act0 -> tpw (fp32)
    }

    // 6) edge tensor product + scatter
    edge_tp_kernel<<<NE, 128>>>(edge_attrs, edge_index);

    // 7) final linear -> message part of output
    msg_kernel<<<NN / 8, 128>>>(W_lin0, W_lin1, out);

    (void)in_sizes; (void)n_in; (void)out_size;
}

// round 12
// speedup vs baseline: 3.1570x; 1.1038x over previous
#include <cuda_runtime.h>
#include <cuda_bf16.h>
#include <math.h>
#include <stdint.h>

#define NN 10000
#define NE 160000
#define CC 128
#define DD 64
#define HID 256
#define TPWN 512
#define MROW 1024          // m0 (256) + m1 (256*3)
#define SC_OFF (NN * 512)  // message is N*128*4 = N*512 floats, sc follows

#define KP1 448            // layer-1 virtual K': [hi 136+8p | lo 136+8p | hi 136+8p | 16p]
#define KPH 768            // hidden virtual K': [hi 256 | lo 256 | hi 256]
#define KACT 512           // stored activation cols: [hi 256 | lo 256]

// -------- device scratch (allocation-free rule: static __device__ globals) ----
// Only referenced from device code (host-side use binds the host shadow; round-5 bug).
__device__ float g_u0[NN * CC];
__device__ float g_u1[NN * CC * 3];
__device__ float g_down[NN * DD];
__device__ float g_tpw[NE * TPWN];
__device__ float g_m[NN * MROW];

__device__ __align__(16) __nv_bfloat16 g_act0[(size_t)NE * KACT];  // ping [hi|lo]
__device__ __align__(16) __nv_bfloat16 g_act1[(size_t)NE * KACT];  // pong
__device__ __align__(16) __nv_bfloat16 g_w1T[HID * KP1];           // W1^T split [256][448]
__device__ __align__(16) __nv_bfloat16 g_w2T[HID * KPH];           // [256][768] [hi|hi|lo]
__device__ __align__(16) __nv_bfloat16 g_w3T[HID * KPH];
__device__ __align__(16) __nv_bfloat16 g_w4T[TPWN * KPH];          // [512][768]

// ======================= warp-MMA helpers (sm_80+ ISA only) =================
__device__ __forceinline__ uint32_t smem_u32(const void* p) {
    uint32_t a;
    asm("{ .reg .u64 t; cvta.to.shared.u64 t, %1; cvt.u32.u64 %0, t; }" : "=r"(a) : "l"(p));
    return a;
}
#define SW128(off) ((off) ^ (((off) >> 3) & 0x70))

__device__ __forceinline__ void ldm_x4(uint32_t* r, uint32_t addr) {
    asm volatile("ldmatrix.sync.aligned.m8n8.x4.shared.b16 {%0,%1,%2,%3}, [%4];"
                 : "=r"(r[0]), "=r"(r[1]), "=r"(r[2]), "=r"(r[3]) : "r"(addr));
}
__device__ __forceinline__ void mma16816(float* c, const uint32_t* a, const uint32_t* b) {
    asm volatile(
        "mma.sync.aligned.m16n8k16.row.col.f32.bf16.bf16.f32 "
        "{%0,%1,%2,%3}, {%4,%5,%6,%7}, {%8,%9}, {%0,%1,%2,%3};"
        : "+f"(c[0]), "+f"(c[1]), "+f"(c[2]), "+f"(c[3])
        : "r"(a[0]), "r"(a[1]), "r"(a[2]), "r"(a[3]), "r"(b[0]), "r"(b[1]));
}
__device__ __forceinline__ void cp16(uint32_t dst, const void* src) {
    asm volatile("cp.async.cg.shared.global [%0], [%1], 16;" :: "r"(dst), "l"(src));
}
#define CP_COMMIT() asm volatile("cp.async.commit_group;" ::: "memory")
#define CP_WAIT1()  asm volatile("cp.async.wait_group 1;" ::: "memory")
#define CP_WAIT0()  asm volatile("cp.async.wait_group 0;" ::: "memory")

// ---------------------------------------------------------------------------
// zero the segment-sum accumulator (must run every launch: deterministic)
// ---------------------------------------------------------------------------
__global__ void zero_m_kernel() {
    int idx = blockIdx.x * blockDim.x + threadIdx.x;
    int stride = gridDim.x * blockDim.x;
    for (int i = idx; i < NN * MROW; i += stride) g_m[i] = 0.0f;
}

// ---------------------------------------------------------------------------
// Node transforms: u0, u1, down (to scratch) + sc (directly to output)
// ---------------------------------------------------------------------------
__global__ void node_kernel(const float* __restrict__ nf,
                            const float* __restrict__ Wu0,
                            const float* __restrict__ Wu1,
                            const float* __restrict__ Wd,
                            const float* __restrict__ Ws0,
                            const float* __restrict__ Ws1,
                            float* __restrict__ out) {
    const int NB = 8;
    __shared__ float sx0[NB][CC];
    __shared__ float sx1[NB][CC * 3];
    int n0 = blockIdx.x * NB;
    int v = threadIdx.x;  // 0..127

    for (int j = v; j < NB * 512; j += 128) {
        int nb = j >> 9;
        int k = j & 511;
        float val = nf[(size_t)(n0 + nb) * 512 + k];
        if (k < 128) sx0[nb][k] = val;
        else sx1[nb][k - 128] = val;
    }
    __syncthreads();

    const float inv_c = 0.08838834764831845f;  // 1/sqrt(128)

    float au0[NB], as0[NB], ad[NB];
#pragma unroll
    for (int nb = 0; nb < NB; nb++) { au0[nb] = 0.f; as0[nb] = 0.f; ad[nb] = 0.f; }
    for (int u = 0; u < CC; u++) {
        float w0 = Wu0[u * CC + v];
        float ws = Ws0[u * CC + v];
        float wd = (v < DD) ? Wd[u * DD + v] : 0.f;
#pragma unroll
        for (int nb = 0; nb < NB; nb++) {
            float x = sx0[nb][u];
            au0[nb] += x * w0;
            as0[nb] += x * ws;
            ad[nb] += x * wd;
        }
    }
#pragma unroll
    for (int nb = 0; nb < NB; nb++) {
        int n = n0 + nb;
        g_u0[n * CC + v] = au0[nb] * inv_c;
        out[SC_OFF + (size_t)n * 512 + v] = as0[nb] * inv_c;
        if (v < DD) g_down[n * DD + v] = ad[nb] * inv_c;
    }

    float au1[NB][3], as1[NB][3];
#pragma unroll
    for (int nb = 0; nb < NB; nb++)
#pragma unroll
        for (int i = 0; i < 3; i++) { au1[nb][i] = 0.f; as1[nb][i] = 0.f; }
    for (int u = 0; u < CC; u++) {
        float wu = Wu1[u * CC + v];
        float ws = Ws1[u * CC + v];
#pragma unroll
        for (int nb = 0; nb < NB; nb++) {
#pragma unroll
            for (int i = 0; i < 3; i++) {
                float x = sx1[nb][u * 3 + i];
                au1[nb][i] += x * wu;
                as1[nb][i] += x * ws;
            }
        }
    }
#pragma unroll
    for (int nb = 0; nb < NB; nb++) {
        int n = n0 + nb;
#pragma unroll
        for (int i = 0; i < 3; i++) {
            g_u1[n * (CC * 3) + v * 3 + i] = au1[nb][i] * inv_c;
            out[SC_OFF + (size_t)n * 512 + 128 + v * 3 + i] = as1[nb][i] * inv_c;
        }
    }
}

// ---------------------------------------------------------------------------
// Weight prep: transpose to [N][K'] K-major bf16 with split segments.
// ---------------------------------------------------------------------------
__global__ void prep_w1(const float* __restrict__ w) {  // [136][256] -> g_w1T [256][448]
    int i = blockIdx.x * blockDim.x + threadIdx.x;
    if (i >= HID * KP1) return;
    int n = i / KP1, k = i % KP1;
    __nv_bfloat16 o = __float2bfloat16(0.f);
    if (k < 432) {
        int seg = k / 144, rem = k % 144;
        if (rem < 136) {
            float v = w[rem * HID + n];
            __nv_bfloat16 h = __float2bfloat16(v);
            o = (seg < 2) ? h : __float2bfloat16(v - __bfloat162float(h));
        }
    }
    g_w1T[n * KP1 + k] = o;
}

template <int WSEL>  // 2,3,4
__global__ void prep_w_hid(const float* __restrict__ w, int Nc) {
    int i = blockIdx.x * blockDim.x + threadIdx.x;
    if (i >= Nc * KPH) return;
    int n = i / KPH, k = i % KPH;
    int seg = k >> 8, rem = k & 255;
    float v = w[rem * Nc + n];
    __nv_bfloat16 h = __float2bfloat16(v);
    __nv_bfloat16 o = (seg < 2) ? h : __float2bfloat16(v - __bfloat162float(h));
    __nv_bfloat16* dst = (WSEL == 2) ? g_w2T : (WSEL == 3) ? g_w3T : g_w4T;
    dst[(size_t)n * KPH + k] = o;
}

// ---------------------------------------------------------------------------
// HMMA GEMM: C[128 x 128 tile] = A'[M,K'] @ W'[N,K']^T, fp32 accum.
// 8 warps: 4(M) x 2(N) -> warp tile 32x64. mma.m16n8k16 bf16, ldmatrix feeds.
// 3-stage cp.async ring, K staged 64 bf16 (128B SW128 rows).
// SRC 0: A gathered+split on the fly from fp32 (edge_feats | down[s] | down[r]).
// SRC 1/2: A = g_act0/g_act1 stored [hi|lo]; virtual col>=512 re-reads hi.
// DST 0/1 -> silu + bf16 hi/lo split into g_act0/g_act1; 2 -> fp32 g_tpw.
// ---------------------------------------------------------------------------
template <int SRC, int WSEL, int DST, int KPRM, bool SILU>
__global__ void __launch_bounds__(256)
mma_gemm(float scale, const float* __restrict__ ef, const int* __restrict__ eidx) {
    const __nv_bfloat16* __restrict__ A =
        (SRC == 1) ? g_act0 : (SRC == 2) ? g_act1 : nullptr;
    const __nv_bfloat16* __restrict__ W =
        (WSEL == 1) ? g_w1T : (WSEL == 2) ? g_w2T : (WSEL == 3) ? g_w3T : g_w4T;
    const int WK = (WSEL == 1) ? KP1 : KPH;  // weight row stride

    extern __shared__ char smem[];
    const int BOFF = 49152;  // A: 3 x 16KB, B: 3 x 16KB
    uint32_t sb = smem_u32(smem);

    int tid = threadIdx.x;
    int lane = tid & 31, wid = tid >> 5;
    int wm = wid & 3;        // 0..3 -> M offset wm*32
    int wn = wid >> 2;       // 0..1 -> N offset wn*64
    int rowBase = blockIdx.y * 128;
    int colBase = blockIdx.x * 128;
    const int S = KPRM / 64;

    float acc[2][8][4];
#pragma unroll
    for (int i = 0; i < 2; i++)
#pragma unroll
        for (int j = 0; j < 8; j++)
#pragma unroll
            for (int q = 0; q < 4; q++) acc[i][j][q] = 0.f;

    // ---- stage loader: A tile 128x64 bf16 + B tile 128x64 bf16, SW128 ----
    auto load_stage = [&](int ks, int buf) {
        char* as = smem + buf * 16384;
        uint32_t bBase = sb + BOFF + buf * 16384;
        uint32_t aBase = sb + buf * 16384;
#pragma unroll
        for (int c = 0; c < 4; c++) {
            int idx = tid + c * 256;           // 0..1023
            int row = idx >> 3, cb = idx & 7;  // 128 rows x 8 chunks of 8 bf16
            int c0 = ks * 64 + cb * 8;
            uint32_t so = SW128((uint32_t)(row * 128 + cb * 16));
            // ---- A ----
            if (SRC == 0) {
                float v[8];
                bool zero = (c0 >= 432);
                int seg = 0;
                if (!zero) {
                    seg = c0 / 144;            // 0,1,2
                    int j = c0 - seg * 144;
                    const float* src = nullptr;
                    int e = rowBase + row;
                    if (j < 8) src = ef + (size_t)e * 8 + j;
                    else if (j < 72) src = g_down + (size_t)eidx[e] * DD + (j - 8);
                    else if (j < 136) src = g_down + (size_t)eidx[NE + e] * DD + (j - 72);
                    else zero = true;          // pad cols 136..143 within segment
                    if (!zero) {
                        float4 v0 = *(const float4*)src;
                        float4 v1 = *(const float4*)(src + 4);
                        v[0] = v0.x; v[1] = v0.y; v[2] = v0.z; v[3] = v0.w;
                        v[4] = v1.x; v[5] = v1.y; v[6] = v1.z; v[7] = v1.w;
                    }
                }
                uint4 wv;
                if (zero) {
                    wv = make_uint4(0u, 0u, 0u, 0u);
                } else {
                    uint32_t pk[4];
#pragma unroll
                    for (int t = 0; t < 4; t++) {
                        __nv_bfloat16 h0 = __float2bfloat16(v[2 * t]);
                        __nv_bfloat16 h1 = __float2bfloat16(v[2 * t + 1]);
                        __nv_bfloat162 p;
                        if (seg == 1) {
                            p.x = __float2bfloat16(v[2 * t] - __bfloat162float(h0));
                            p.y = __float2bfloat16(v[2 * t + 1] - __bfloat162float(h1));
                        } else {
                            p.x = h0; p.y = h1;
                        }
                        pk[t] = *(uint32_t*)&p;
                    }
                    wv = make_uint4(pk[0], pk[1], pk[2], pk[3]);
                }
                *(uint4*)(as + so) = wv;
            } else {
                int srccol = (c0 < KACT) ? c0 : c0 - KACT;  // hi copy re-read
                cp16(aBase + so, A + (size_t)(rowBase + row) * KACT + srccol);
            }
            // ---- B (always dense, cp.async) ----
            cp16(bBase + so, W + (size_t)(colBase + row) * WK + c0);
        }
        CP_COMMIT();
    };

    load_stage(0, 0);
    if (S > 1) load_stage(1, 1);

    for (int s = 0; s < S; s++) {
        if (s + 1 < S) { CP_WAIT1(); } else { CP_WAIT0(); }
        __syncthreads();

        int buf = s % 3;
        uint32_t aBase = sb + buf * 16384;
        uint32_t bBase = sb + BOFF + buf * 16384;
#pragma unroll
        for (int k16 = 0; k16 < 4; k16++) {
            uint32_t a[2][4];
#pragma unroll
            for (int mf = 0; mf < 2; mf++) {
                int r = wm * 32 + mf * 16 + (lane & 15);
                int kc = k16 * 16 + ((lane >> 4) << 3);
                ldm_x4(a[mf], aBase + SW128((uint32_t)(r * 128 + kc * 2)));
            }
            uint32_t b[8][2];
#pragma unroll
            for (int g = 0; g < 4; g++) {
                int nr = wn * 64 + g * 16 + (lane & 7) + ((lane >> 4) & 1) * 8;
                int kc = k16 * 16 + (((lane >> 3) & 1) << 3);
                uint32_t t4[4];
                ldm_x4(t4, bBase + SW128((uint32_t)(nr * 128 + kc * 2)));
                b[2 * g][0] = t4[0]; b[2 * g][1] = t4[1];
                b[2 * g + 1][0] = t4[2]; b[2 * g + 1][1] = t4[3];
            }
#pragma unroll
            for (int mf = 0; mf < 2; mf++)
#pragma unroll
                for (int nf = 0; nf < 8; nf++)
                    mma16816(acc[mf][nf], a[mf], b[nf]);
        }
        __syncthreads();  // all reads of buf done before refill

        if (s + 2 < S) load_stage(s + 2, (s + 2) % 3);
    }

    // ---- epilogue: frag (mf,nf): rows r0,r0+8; cols c0,c0+1 ----
#pragma unroll
    for (int mf = 0; mf < 2; mf++) {
#pragma unroll
        for (int nf = 0; nf < 8; nf++) {
            int r0 = rowBase + wm * 32 + mf * 16 + (lane >> 2);
            int c0 = colBase + wn * 64 + nf * 8 + (lane & 3) * 2;
            if (DST == 2) {
                float2 v0 = make_float2(acc[mf][nf][0] * scale, acc[mf][nf][1] * scale);
                float2 v1 = make_float2(acc[mf][nf][2] * scale, acc[mf][nf][3] * scale);
                *(float2*)(g_tpw + (size_t)r0 * TPWN + c0) = v0;
                *(float2*)(g_tpw + (size_t)(r0 + 8) * TPWN + c0) = v1;
            } else {
                __nv_bfloat16* dst = (DST == 0) ? g_act0 : g_act1;
#pragma unroll
                for (int rr = 0; rr < 2; rr++) {
                    float x0 = acc[mf][nf][rr * 2 + 0] * scale;
                    float x1 = acc[mf][nf][rr * 2 + 1] * scale;
                    if (SILU) {
                        x0 = x0 / (1.0f + expf(-x0));
                        x1 = x1 / (1.0f + expf(-x1));
                    }
                    __nv_bfloat16 h0 = __float2bfloat16(x0);
                    __nv_bfloat16 h1 = __float2bfloat16(x1);
                    __nv_bfloat162 hp; hp.x = h0; hp.y = h1;
                    __nv_bfloat162 lp;
                    lp.x = __float2bfloat16(x0 - __bfloat162float(h0));
                    lp.y = __float2bfloat16(x1 - __bfloat162float(h1));
                    __nv_bfloat16* p = dst + (size_t)(r0 + rr * 8) * KACT + c0;
                    *(__nv_bfloat162*)(p) = hp;          // hi segment [0,256)
                    *(__nv_bfloat162*)(p + 256) = lp;    // lo segment [256,512)
                }
            }
        }
    }
}

// ---------------------------------------------------------------------------
// Edge tensor product + scatter-add (segment_sum) into g_m
// ---------------------------------------------------------------------------
__global__ void edge_tp_kernel(const float* __restrict__ edge_attrs,
                               const int* __restrict__ edge_index) {
    int e = blockIdx.x;
    int c = threadIdx.x;

    int s = edge_index[e];
    int r = edge_index[NE + e];
    float4 y = *(const float4*)(edge_attrs + (size_t)e * 4);
    float y0 = y.x, y1x = y.y, y1y = y.z, y1z = y.w;

    const float* tw = g_tpw + (size_t)e * TPWN;
    float w0 = tw[c];
    float w1 = tw[128 + c];
    float w2 = tw[256 + c];
    float w3 = tw[384 + c];

    float xs0 = g_u0[(size_t)s * CC + c];
    const float* u1p = g_u1 + (size_t)s * (CC * 3) + c * 3;
    float x1a = u1p[0], x1b = u1p[1], x1c = u1p[2];

    float* mrow = g_m + (size_t)r * MROW;
    const float rsqrt3 = 0.5773502691896258f;

    atomicAdd(mrow + c, w0 * xs0 * y0);
    float dot = x1a * y1x + x1b * y1y + x1c * y1z;
    atomicAdd(mrow + 128 + c, w3 * dot * rsqrt3);
    float a = w1 * xs0;
    atomicAdd(mrow + 256 + c * 3 + 0, a * y1x);
    atomicAdd(mrow + 256 + c * 3 + 1, a * y1y);
    atomicAdd(mrow + 256 + c * 3 + 2, a * y1z);
    float b = w2 * y0;
    atomicAdd(mrow + 256 + (128 + c) * 3 + 0, b * x1a);
    atomicAdd(mrow + 256 + (128 + c) * 3 + 1, b * x1b);
    atomicAdd(mrow + 256 + (128 + c) * 3 + 2, b * x1c);
}

// ---------------------------------------------------------------------------
// Final linear: message[n,v,0] = (m0 @ Wl0)/256 ; message[n,v,1..3] = (m1 @ Wl1)/256
// ---------------------------------------------------------------------------
__global__ void msg_kernel(const float* __restrict__ Wl0,
                           const float* __restrict__ Wl1,
                           float* __restrict__ out) {
    const int NB = 8;
    __shared__ float sm[NB][MROW];
    int n0 = blockIdx.x * NB;
    int v = threadIdx.x;

    for (int j = v; j < NB * MROW; j += 128) {
        sm[j >> 10][j & 1023] = g_m[(size_t)n0 * MROW + j];
    }
    __syncthreads();

    float m0acc[NB];
    float m1acc[NB][3];
#pragma unroll
    for (int nb = 0; nb < NB; nb++) {
        m0acc[nb] = 0.f;
#pragma unroll
        for (int i = 0; i < 3; i++) m1acc[nb][i] = 0.f;
    }

    for (int cc = 0; cc < 256; cc++) {
        float w0 = Wl0[cc * 128 + v];
        float w1 = Wl1[cc * 128 + v];
#pragma unroll
        for (int nb = 0; nb < NB; nb++) {
            m0acc[nb] += sm[nb][cc] * w0;
#pragma unroll
            for (int i = 0; i < 3; i++)
                m1acc[nb][i] += sm[nb][256 + cc * 3 + i] * w1;
        }
    }

    const float sc = 1.0f / 256.0f;  // (1/sqrt(256)) / AVG_NEIGH
#pragma unroll
    for (int nb = 0; nb < NB; nb++) {
        int n = n0 + nb;
        float4 v4;
        v4.x = m0acc[nb] * sc;
        v4.y = m1acc[nb][0] * sc;
        v4.z = m1acc[nb][1] * sc;
        v4.w = m1acc[nb][2] * sc;
        *(float4*)(out + (size_t)n * 512 + v * 4) = v4;
    }
}

// ---------------------------------------------------------------------------
extern "C" void kernel_launch(void* const* d_in, const int* in_sizes, int n_in,
                              void* d_out, int out_size) {
    const float* node_feats = (const float*)d_in[1];
    const float* edge_attrs = (const float*)d_in[2];
    const float* edge_feats = (const float*)d_in[3];
    const int*   edge_index = (const int*)d_in[4];
    const float* W_up0  = (const float*)d_in[5];
    const float* W_up1  = (const float*)d_in[6];
    const float* W_down = (const float*)d_in[7];
    const float* mlp_w1 = (const float*)d_in[8];
    const float* mlp_w2 = (const float*)d_in[9];
    const float* mlp_w3 = (const float*)d_in[10];
    const float* mlp_w4 = (const float*)d_in[11];
    const float* W_lin0 = (const float*)d_in[12];
    const float* W_lin1 = (const float*)d_in[13];
    const float* W_skip0 = (const float*)d_in[14];
    const float* W_skip1 = (const float*)d_in[15];
    float* out = (float*)d_out;

    const int MM_SMEM = 98304;  // 3x16KB A + 3x16KB B
    cudaFuncSetAttribute(mma_gemm<0, 1, 0, KP1, true>,
                         cudaFuncAttributeMaxDynamicSharedMemorySize, MM_SMEM);
    cudaFuncSetAttribute(mma_gemm<1, 2, 1, KPH, true>,
                         cudaFuncAttributeMaxDynamicSharedMemorySize, MM_SMEM);
    cudaFuncSetAttribute(mma_gemm<2, 3, 0, KPH, true>,
                         cudaFuncAttributeMaxDynamicSharedMemorySize, MM_SMEM);
    cudaFuncSetAttribute(mma_gemm<1, 4, 2, KPH, false>,
                         cudaFuncAttributeMaxDynamicSharedMemorySize, MM_SMEM);

    // 1) zero segment-sum accumulator
    zero_m_kernel<<<512, 256>>>();

    // 2) node transforms (+ sc output); produces g_down for layer-1 gather
    node_kernel<<<NN / 8, 128>>>(node_feats, W_up0, W_up1, W_down, W_skip0, W_skip1, out);

    // 3) weight prep (transpose + bf16 hi/lo split)
    prep_w1<<<(HID * KP1 + 255) / 256, 256>>>(mlp_w1);
    prep_w_hid<2><<<(HID * KPH + 255) / 256, 256>>>(mlp_w2, HID);
    prep_w_hid<3><<<(HID * KPH + 255) / 256, 256>>>(mlp_w3, HID);
    prep_w_hid<4><<<(TPWN * KPH + 255) / 256, 256>>>(mlp_w4, TPWN);

    // 4) edge MLP on HMMA tensor cores (fp32-accurate via 3-term bf16 split);
    //    layer-1 gathers its operand on the fly (no prep_aug materialization)
    float scale1 = 1.0f / sqrtf(136.0f);
    float scale2 = 1.0f / 16.0f;
    {
        dim3 g(HID / 128, NE / 128);   // (2, 1250)
        mma_gemm<0, 1, 0, KP1, true><<<g, 256, MM_SMEM>>>(scale1, edge_feats, edge_index);
        mma_gemm<1, 2, 1, KPH, true><<<g, 256, MM_SMEM>>>(scale2, nullptr, nullptr);
        mma_gemm<2, 3, 0, KPH, true><<<g, 256, MM_SMEM>>>(scale2, nullptr, nullptr);
    }
    {
        dim3 g(TPWN / 128, NE / 128);  // (4, 1250)
        mma_gemm<1, 4, 2, KPH, false><<<g, 256, MM_SMEM>>>(scale2, nullptr, nullptr);
    }

    // 5) edge tensor product + scatter
    edge_tp_kernel<<<NE, 128>>>(edge_attrs, edge_index);

    // 6) final linear -> message part of output
    msg_kernel<<<NN / 8, 128>>>(W_lin0, W_lin1, out);

    (void)in_sizes; (void)n_in; (void)out_size;
}